// round 17
// baseline (speedup 1.0000x reference)
#include <cuda_runtime.h>
#include <cuda_bf16.h>
#include <math.h>
#include <stdint.h>

#define Bb 2
#define Tt 2048
#define Dd 1024
#define Hh 16
#define Kknn 3
#define Mm 16384
#define HDd 64
#define Nn (Bb*Tt)          // 4096 rows
#define SCALE_F 4096.0f     // D * sqrt(H)

// ---------------- scratch (device globals; no allocation allowed) ----------------
__device__ float g_q[Nn*Dd];
__device__ float g_k[Nn*Dd];
__device__ float g_v[Nn*Dd];
__device__ float g_o[Nn*Dd];
__device__ __nv_bfloat16 g_obf[Nn*Dd];     // combined, exact bf16
__device__ __nv_bfloat16 g_xh[Nn*Dd];      // x split bf16 hi/lo (V proj)
__device__ __nv_bfloat16 g_xl[Nn*Dd];
__device__ __nv_bfloat16 g_wvh[Dd*Dd];
__device__ __nv_bfloat16 g_wvl[Dd*Dd];
__device__ __nv_bfloat16 g_woh[Dd*Dd];
__device__ __nv_bfloat16 g_wol[Dd*Dd];
// interleaved tf32 (hi,lo) fp32 planes: [i] -> (hi at 2i, lo at 2i+1)
__device__ float g_xs [Nn*Dd*2];
__device__ float g_wqs[Dd*Dd*2];
__device__ float g_wks[Dd*Dd*2];

// ================= helpers ===================
__device__ __forceinline__ void mma_tf32(float* c, const uint32_t* a, const uint32_t* b)
{
    asm volatile(
        "mma.sync.aligned.m16n8k8.row.col.f32.tf32.tf32.f32 "
        "{%0,%1,%2,%3}, {%4,%5,%6,%7}, {%8,%9}, {%0,%1,%2,%3};\n"
        : "+f"(c[0]), "+f"(c[1]), "+f"(c[2]), "+f"(c[3])
        : "r"(a[0]), "r"(a[1]), "r"(a[2]), "r"(a[3]), "r"(b[0]), "r"(b[1]));
}

__device__ __forceinline__ void mma_bf16(float* c, const uint32_t* a, const uint32_t* b)
{
    asm volatile(
        "mma.sync.aligned.m16n8k16.row.col.f32.bf16.bf16.f32 "
        "{%0,%1,%2,%3}, {%4,%5,%6,%7}, {%8,%9}, {%0,%1,%2,%3};\n"
        : "+f"(c[0]), "+f"(c[1]), "+f"(c[2]), "+f"(c[3])
        : "r"(a[0]), "r"(a[1]), "r"(a[2]), "r"(a[3]), "r"(b[0]), "r"(b[1]));
}

__device__ __forceinline__ void split3(float x, uint32_t& h, uint32_t& l)
{
    uint32_t xh = __float_as_uint(x) & 0xffffe000u;
    h = xh;
    l = __float_as_uint(x - __uint_as_float(xh));
}

// pack two floats to bf16x2 (elem0 in low half)
__device__ __forceinline__ uint32_t pack_bf16(float e0, float e1)
{
    uint32_t r;
    asm("cvt.rn.bf16x2.f32 %0, %1, %2;" : "=r"(r) : "f"(e1), "f"(e0));
    return r;
}

// e^x via exp2 poly on the FMA pipe (no MUFU). Accurate to ~3e-6 rel.
__device__ __forceinline__ float fexp(float x)
{
    float t = x * 1.4426950408889634f;
    t = fmaxf(t, -126.0f);
    float r = rintf(t);
    float f = t - r;
    float p = 0.0013333558146428443f;
    p = fmaf(p, f, 0.009618129107628477f);
    p = fmaf(p, f, 0.05550410866482158f);
    p = fmaf(p, f, 0.2402265069591007f);
    p = fmaf(p, f, 0.6931471805599453f);
    p = fmaf(p, f, 1.0f);
    int e = (int)r;
    float s = __int_as_float((e + 127) << 23);
    return s * p;
}

// ---------------- split fp32 -> bf16 hi + bf16 lo (planes) ----------------
__global__ __launch_bounds__(256) void split_kernel(
    const float* __restrict__ src, __nv_bfloat16* __restrict__ dh,
    __nv_bfloat16* __restrict__ dl, int n4)
{
    int i = blockIdx.x * 256 + threadIdx.x;
    if (i >= n4) return;
    float4 v = ((const float4*)src)[i];
    uint32_t h0 = pack_bf16(v.x, v.y);
    uint32_t h1 = pack_bf16(v.z, v.w);
    float fx = __uint_as_float(h0 << 16);
    float fy = __uint_as_float(h0 & 0xffff0000u);
    float fz = __uint_as_float(h1 << 16);
    float fw = __uint_as_float(h1 & 0xffff0000u);
    uint32_t l0 = pack_bf16(v.x - fx, v.y - fy);
    uint32_t l1 = pack_bf16(v.z - fz, v.w - fw);
    ((uint2*)dh)[i] = make_uint2(h0, h1);
    ((uint2*)dl)[i] = make_uint2(l0, l1);
}

// ---------------- split fp32 -> interleaved tf32 (hi,lo) fp32 pairs -------------
__global__ __launch_bounds__(256) void split_tf32_kernel(
    const float* __restrict__ src, float* __restrict__ dst, int n4)
{
    int i = blockIdx.x * 256 + threadIdx.x;
    if (i >= n4) return;
    float4 v = ((const float4*)src)[i];
    uint32_t hx, lx, hy, ly, hz, lz, hw, lw;
    split3(v.x, hx, lx); split3(v.y, hy, ly);
    split3(v.z, hz, lz); split3(v.w, hw, lw);
    float4 o0, o1;
    o0.x = __uint_as_float(hx); o0.y = __uint_as_float(lx);
    o0.z = __uint_as_float(hy); o0.w = __uint_as_float(ly);
    o1.x = __uint_as_float(hz); o1.y = __uint_as_float(lz);
    o1.z = __uint_as_float(hw); o1.w = __uint_as_float(lw);
    ((float4*)dst)[2 * i]     = o0;
    ((float4*)dst)[2 * i + 1] = o1;
}

// ================= GEMM (3xTF32, pre-split interleaved planes): Q, K proj ========
// A2/W2: [row][2*Dd] interleaved (hi,lo). Inner loop: pure LDS.64 + MMA.
// BK=16. smem row = 16 pairs (32 floats) + 8 pad = 40.
#define ILD 40

__global__ __launch_bounds__(256, 2) void gemm_tf32ps_kernel(
    const float* __restrict__ A2,
    const float* __restrict__ W2_0, const float* __restrict__ b0, float* __restrict__ C0,
    const float* __restrict__ W2_1, const float* __restrict__ b1, float* __restrict__ C1)
{
    const float* W2; const float* bias; float* C;
    if (blockIdx.z == 0) { W2 = W2_0; bias = b0; C = C0; }
    else                 { W2 = W2_1; bias = b1; C = C1; }

    __shared__ float As[128][ILD];
    __shared__ float Bs[128][ILD];

    const int tid  = threadIdx.x;
    const int wid  = tid >> 5, lane = tid & 31;
    const int wm   = wid >> 1;      // 0..3
    const int wn   = wid & 1;       // 0..1
    const int g    = lane >> 2;     // 0..7
    const int tg   = lane & 3;      // 0..3
    const int row0 = blockIdx.y * 128;
    const int col0 = blockIdx.x * 128;

    // loader: thread t -> row lr = t>>1, float-offset lh = (t&1)*16, 4 float4
    const int lr = tid >> 1;
    const int lh = (tid & 1) * 16;
    const float* Ag = A2 + (size_t)(row0 + lr) * (2 * Dd) + lh;
    const float* Wg = W2 + (size_t)(col0 + lr) * (2 * Dd) + lh;

    float4 pa[4], pb[4];
#pragma unroll
    for (int p = 0; p < 4; p++) {
        pa[p] = *(const float4*)(Ag + 4 * p);
        pb[p] = *(const float4*)(Wg + 4 * p);
    }

    float acc[2][8][4];
#pragma unroll
    for (int mt = 0; mt < 2; mt++)
#pragma unroll
        for (int nt = 0; nt < 8; nt++)
#pragma unroll
            for (int r = 0; r < 4; r++) acc[mt][nt][r] = 0.f;

    const int NKT = Dd / 16;   // 64 iterations, 32 interleaved floats each
    for (int kt = 0; kt < NKT; kt++) {
#pragma unroll
        for (int p = 0; p < 4; p++) {
            *(float4*)&As[lr][lh + 4 * p] = pa[p];
            *(float4*)&Bs[lr][lh + 4 * p] = pb[p];
        }
        __syncthreads();
        if (kt < NKT - 1) {
            const int ko = (kt + 1) * 32;
#pragma unroll
            for (int p = 0; p < 4; p++) {
                pa[p] = *(const float4*)(Ag + ko + 4 * p);
                pb[p] = *(const float4*)(Wg + ko + 4 * p);
            }
        }
#pragma unroll
        for (int ks = 0; ks < 2; ks++) {
            const int k2 = ks * 16;           // float offset of 8-wide k group
            uint32_t ah[2][4], al[2][4];
#pragma unroll
            for (int mt = 0; mt < 2; mt++) {
                const int m = wm * 32 + mt * 16;
                float2 a0 = *(const float2*)&As[m + g    ][k2 + 2 * tg    ];
                float2 a1 = *(const float2*)&As[m + 8 + g][k2 + 2 * tg    ];
                float2 a2 = *(const float2*)&As[m + g    ][k2 + 2 * tg + 8];
                float2 a3 = *(const float2*)&As[m + 8 + g][k2 + 2 * tg + 8];
                ah[mt][0] = __float_as_uint(a0.x); al[mt][0] = __float_as_uint(a0.y);
                ah[mt][1] = __float_as_uint(a1.x); al[mt][1] = __float_as_uint(a1.y);
                ah[mt][2] = __float_as_uint(a2.x); al[mt][2] = __float_as_uint(a2.y);
                ah[mt][3] = __float_as_uint(a3.x); al[mt][3] = __float_as_uint(a3.y);
            }
#pragma unroll
            for (int nt = 0; nt < 8; nt++) {
                const int n = wn * 64 + nt * 8 + g;
                float2 b0 = *(const float2*)&Bs[n][k2 + 2 * tg    ];
                float2 b1 = *(const float2*)&Bs[n][k2 + 2 * tg + 8];
                uint32_t bh[2], bl[2];
                bh[0] = __float_as_uint(b0.x); bl[0] = __float_as_uint(b0.y);
                bh[1] = __float_as_uint(b1.x); bl[1] = __float_as_uint(b1.y);
#pragma unroll
                for (int mt = 0; mt < 2; mt++) {
                    mma_tf32(acc[mt][nt], al[mt], bh);
                    mma_tf32(acc[mt][nt], ah[mt], bl);
                    mma_tf32(acc[mt][nt], ah[mt], bh);
                }
            }
        }
        __syncthreads();
    }

#pragma unroll
    for (int mt = 0; mt < 2; mt++) {
        const int r = row0 + wm * 32 + mt * 16 + g;
#pragma unroll
        for (int nt = 0; nt < 8; nt++) {
            const int c = col0 + wn * 64 + nt * 8 + tg * 2;
            const float bb0 = bias[c], bb1 = bias[c + 1];
            float2 v0 = make_float2(acc[mt][nt][0] + bb0, acc[mt][nt][1] + bb1);
            float2 v1 = make_float2(acc[mt][nt][2] + bb0, acc[mt][nt][3] + bb1);
            *(float2*)&C[(size_t)r * Dd + c]       = v0;
            *(float2*)&C[(size_t)(r + 8) * Dd + c] = v1;
        }
    }
}

// ================= GEMM (bf16 pre-split planes): V proj (3x) & output proj (2x) ==
#define BLDA 40   // bf16 elements per smem row

template<int USE_AL>
__global__ __launch_bounds__(256) void gemm_bf16_kernel(
    const __nv_bfloat16* __restrict__ Ah, const __nv_bfloat16* __restrict__ Al,
    const __nv_bfloat16* __restrict__ Bh, const __nv_bfloat16* __restrict__ Bl,
    const float* __restrict__ bias, float* __restrict__ C)
{
    __shared__ __align__(16) uint16_t sAh[128][BLDA];
    __shared__ __align__(16) uint16_t sAl[128][BLDA];
    __shared__ __align__(16) uint16_t sBh[128][BLDA];
    __shared__ __align__(16) uint16_t sBl[128][BLDA];

    const int tid  = threadIdx.x;
    const int wid  = tid >> 5, lane = tid & 31;
    const int wm   = wid >> 1;
    const int wn   = wid & 1;
    const int g    = lane >> 2;
    const int tg   = lane & 3;
    const int row0 = blockIdx.y * 128;
    const int col0 = blockIdx.x * 128;

    const int lrow = tid >> 1;
    const int lpart = (tid & 1) * 16;
    const __nv_bfloat16* gAh = Ah + (size_t)(row0 + lrow) * Dd + lpart;
    const __nv_bfloat16* gAl = USE_AL ? (Al + (size_t)(row0 + lrow) * Dd + lpart) : gAh;
    const __nv_bfloat16* gBh = Bh + (size_t)(col0 + lrow) * Dd + lpart;
    const __nv_bfloat16* gBl = Bl + (size_t)(col0 + lrow) * Dd + lpart;

    uint4 pah[2], pal[2], pbh[2], pbl[2];
#pragma unroll
    for (int p = 0; p < 2; p++) {
        pah[p] = ((const uint4*)gAh)[p];
        if (USE_AL) pal[p] = ((const uint4*)gAl)[p];
        pbh[p] = ((const uint4*)gBh)[p];
        pbl[p] = ((const uint4*)gBl)[p];
    }

    float acc[2][8][4];
#pragma unroll
    for (int mt = 0; mt < 2; mt++)
#pragma unroll
        for (int nt = 0; nt < 8; nt++)
#pragma unroll
            for (int r = 0; r < 4; r++) acc[mt][nt][r] = 0.f;

    for (int kt = 0; kt < Dd / 32; kt++) {
#pragma unroll
        for (int p = 0; p < 2; p++) {
            *(uint4*)&sAh[lrow][lpart + p * 8] = pah[p];
            if (USE_AL) *(uint4*)&sAl[lrow][lpart + p * 8] = pal[p];
            *(uint4*)&sBh[lrow][lpart + p * 8] = pbh[p];
            *(uint4*)&sBl[lrow][lpart + p * 8] = pbl[p];
        }
        __syncthreads();
        if (kt < Dd / 32 - 1) {
            const int ko = (kt + 1) * 32;
#pragma unroll
            for (int p = 0; p < 2; p++) {
                pah[p] = ((const uint4*)(gAh + ko))[p];
                if (USE_AL) pal[p] = ((const uint4*)(gAl + ko))[p];
                pbh[p] = ((const uint4*)(gBh + ko))[p];
                pbl[p] = ((const uint4*)(gBl + ko))[p];
            }
        }
#pragma unroll
        for (int half = 0; half < 2; half++) {
            const int k = half * 16;
            uint32_t ah[2][4], al[2][4];
#pragma unroll
            for (int mt = 0; mt < 2; mt++) {
                const int m = wm * 32 + mt * 16;
                ah[mt][0] = *(const uint32_t*)&sAh[m + g    ][k + 2 * tg    ];
                ah[mt][1] = *(const uint32_t*)&sAh[m + 8 + g][k + 2 * tg    ];
                ah[mt][2] = *(const uint32_t*)&sAh[m + g    ][k + 2 * tg + 8];
                ah[mt][3] = *(const uint32_t*)&sAh[m + 8 + g][k + 2 * tg + 8];
                if (USE_AL) {
                    al[mt][0] = *(const uint32_t*)&sAl[m + g    ][k + 2 * tg    ];
                    al[mt][1] = *(const uint32_t*)&sAl[m + 8 + g][k + 2 * tg    ];
                    al[mt][2] = *(const uint32_t*)&sAl[m + g    ][k + 2 * tg + 8];
                    al[mt][3] = *(const uint32_t*)&sAl[m + 8 + g][k + 2 * tg + 8];
                }
            }
#pragma unroll
            for (int nt = 0; nt < 8; nt++) {
                const int n = wn * 64 + nt * 8 + g;
                uint32_t bh[2], bl[2];
                bh[0] = *(const uint32_t*)&sBh[n][k + 2 * tg    ];
                bh[1] = *(const uint32_t*)&sBh[n][k + 2 * tg + 8];
                bl[0] = *(const uint32_t*)&sBl[n][k + 2 * tg    ];
                bl[1] = *(const uint32_t*)&sBl[n][k + 2 * tg + 8];
#pragma unroll
                for (int mt = 0; mt < 2; mt++) {
                    mma_bf16(acc[mt][nt], ah[mt], bh);
                    mma_bf16(acc[mt][nt], ah[mt], bl);
                    if (USE_AL) mma_bf16(acc[mt][nt], al[mt], bh);
                }
            }
        }
        __syncthreads();
    }

#pragma unroll
    for (int mt = 0; mt < 2; mt++) {
        const int r = row0 + wm * 32 + mt * 16 + g;
#pragma unroll
        for (int nt = 0; nt < 8; nt++) {
            const int c = col0 + wn * 64 + nt * 8 + tg * 2;
            const float bb0 = bias[c], bb1 = bias[c + 1];
            float2 v0 = make_float2(acc[mt][nt][0] + bb0, acc[mt][nt][1] + bb1);
            float2 v1 = make_float2(acc[mt][nt][2] + bb0, acc[mt][nt][3] + bb1);
            *(float2*)&C[(size_t)r * Dd + c]       = v0;
            *(float2*)&C[(size_t)(r + 8) * Dd + c] = v1;
        }
    }
}

// ---------------- row L2-normalize over D (q and k, in place) --------------------
__global__ __launch_bounds__(256) void normalize_kernel()
{
    const int row = blockIdx.x;
    float* buf = (blockIdx.y == 0) ? g_q : g_k;
    float* p = buf + (size_t)row * Dd;
    const int tid = threadIdx.x;

    float4 v = *(float4*)(p + tid * 4);
    float ss = v.x * v.x + v.y * v.y + v.z * v.z + v.w * v.w;
#pragma unroll
    for (int o = 16; o; o >>= 1) ss += __shfl_xor_sync(0xffffffffu, ss, o);

    __shared__ float ws[8];
    if ((tid & 31) == 0) ws[tid >> 5] = ss;
    __syncthreads();
    __shared__ float s_inv;
    if (tid == 0) {
        float s = 0.f;
#pragma unroll
        for (int i = 0; i < 8; i++) s += ws[i];
        s_inv = 1.0f / fmaxf(sqrtf(s), 1e-12f);
    }
    __syncthreads();
    float inv = s_inv;
    v.x *= inv; v.y *= inv; v.z *= inv; v.w *= inv;
    *(float4*)(p + tid * 4) = v;
}

// ====== causal flash attention: QK^T 3xTF32 (K pre-split in smem), P·V bf16-3x ===
#define ALD 68    // fp32 smem stride
#define PLD 72    // bf16 smem stride

__global__ __launch_bounds__(256, 2) void attn_kernel()
{
    extern __shared__ float smem[];
    float* Qs = smem;                           // 64 x 68 fp32
    float* Kh = Qs + 64 * ALD;                  // K tf32-hi plane
    float* Kl = Kh + 64 * ALD;                  // K lo plane
    float* Ss = Kl + 64 * ALD;                  // logits fp32
    uint16_t* Vh = (uint16_t*)(Ss + 64 * ALD);  // [n=64][k=72] bf16 (n-major)
    uint16_t* Vl = Vh + 64 * PLD;
    uint16_t* Ph = Vl + 64 * PLD;               // [m=64][j=72] bf16
    uint16_t* Pl = Ph + 64 * PLD;
    __shared__ float sm_m[64], sm_l[64], sm_scale[64];

    const int q0 = blockIdx.x * 64;
    const int h  = blockIdx.y;
    const int b  = blockIdx.z;
    const int tid = threadIdx.x;
    const int wid = tid >> 5, lane = tid & 31;
    const int wm = wid >> 1, wn = wid & 1;
    const int g = lane >> 2, tg = lane & 3;
    const int ty = tid >> 4, tx = tid & 15;

    const float* qbase = g_q + (size_t)(b * Tt) * Dd + h * HDd;
    const float* kbase = g_k + (size_t)(b * Tt) * Dd + h * HDd;
    const float* vbase = g_v + (size_t)(b * Tt) * Dd + h * HDd;

#pragma unroll
    for (int i = 0; i < 4; i++) {
        int r = ty + i * 16;
        float4 v4 = *(const float4*)(qbase + (size_t)(q0 + r) * Dd + tx * 4);
        *(float4*)&Qs[r * ALD + tx * 4] = v4;
    }
    if (tid < 64) { sm_m[tid] = -1e30f; sm_l[tid] = 0.f; }

    float acc[4][4];
#pragma unroll
    for (int nt = 0; nt < 4; nt++)
#pragma unroll
        for (int r = 0; r < 4; r++) acc[nt][r] = 0.f;
    __syncthreads();

    const int ntiles = q0 / 64 + 1;
    for (int jt = 0; jt < ntiles; jt++) {
        const int j0 = jt * 64;
#pragma unroll
        for (int i = 0; i < 4; i++) {
            int r = ty + i * 16;          // token index within tile
            float4 k4 = *(const float4*)(kbase + (size_t)(j0 + r) * Dd + tx * 4);
            // pre-split K into tf32 hi/lo planes (split once, not per-warp)
            float kv[4] = {k4.x, k4.y, k4.z, k4.w};
#pragma unroll
            for (int c = 0; c < 4; c++) {
                uint32_t hh, ll;
                split3(kv[c], hh, ll);
                Kh[r * ALD + tx * 4 + c] = __uint_as_float(hh);
                Kl[r * ALD + tx * 4 + c] = __uint_as_float(ll);
            }
            float4 v4 = *(const float4*)(vbase + (size_t)(j0 + r) * Dd + tx * 4);
            // split V into bf16 planes stored n-major: Vh[n][k]
            float vv[4] = {v4.x, v4.y, v4.z, v4.w};
#pragma unroll
            for (int c = 0; c < 4; c++) {
                int n = tx * 4 + c;
                float f = vv[c];
                __nv_bfloat16 hb = __float2bfloat16(f);
                float fh = __bfloat162float(hb);
                __nv_bfloat16 lb = __float2bfloat16(f - fh);
                Vh[n * PLD + r] = *(uint16_t*)&hb;
                Vl[n * PLD + r] = *(uint16_t*)&lb;
            }
        }
        __syncthreads();

        // ---- S = Q K^T (3xTF32 mma; K planes pre-split) ----
        float sfr[4][4];
#pragma unroll
        for (int nt = 0; nt < 4; nt++)
#pragma unroll
            for (int r = 0; r < 4; r++) sfr[nt][r] = 0.f;

#pragma unroll
        for (int ks = 0; ks < 8; ks++) {
            const int k = ks * 8;
            const int m = wm * 16;
            uint32_t ah[4], al[4];
            split3(Qs[(m + g    ) * ALD + k + tg    ], ah[0], al[0]);
            split3(Qs[(m + g + 8) * ALD + k + tg    ], ah[1], al[1]);
            split3(Qs[(m + g    ) * ALD + k + tg + 4], ah[2], al[2]);
            split3(Qs[(m + g + 8) * ALD + k + tg + 4], ah[3], al[3]);
#pragma unroll
            for (int nt = 0; nt < 4; nt++) {
                const int n = wn * 32 + nt * 8 + g;
                uint32_t bh[2], bl[2];
                bh[0] = *(const uint32_t*)&Kh[n * ALD + k + tg    ];
                bl[0] = *(const uint32_t*)&Kl[n * ALD + k + tg    ];
                bh[1] = *(const uint32_t*)&Kh[n * ALD + k + tg + 4];
                bl[1] = *(const uint32_t*)&Kl[n * ALD + k + tg + 4];
                mma_tf32(sfr[nt], al, bh);
                mma_tf32(sfr[nt], ah, bl);
                mma_tf32(sfr[nt], ah, bh);
            }
        }

        // ---- store S (scaled + causal mask) ----
        const bool diag = (j0 == q0);
        const int rr = wm * 16 + g;
#pragma unroll
        for (int nt = 0; nt < 4; nt++) {
            const int c = wn * 32 + nt * 8 + tg * 2;
            float v0 = sfr[nt][0] * SCALE_F, v1 = sfr[nt][1] * SCALE_F;
            float v2 = sfr[nt][2] * SCALE_F, v3 = sfr[nt][3] * SCALE_F;
            if (diag) {
                if (c     > rr    ) v0 = -1e30f;
                if (c + 1 > rr    ) v1 = -1e30f;
                if (c     > rr + 8) v2 = -1e30f;
                if (c + 1 > rr + 8) v3 = -1e30f;
            }
            Ss[ rr      * ALD + c] = v0; Ss[ rr      * ALD + c + 1] = v1;
            Ss[(rr + 8) * ALD + c] = v2; Ss[(rr + 8) * ALD + c + 1] = v3;
        }
        __syncthreads();

        // ---- softmax: quad-per-row, fast exp, write bf16 hi/lo P planes ----
        {
            const int r = tid >> 2, qd = tid & 3;
            float* rowp = &Ss[r * ALD + qd * 16];
            float x[16];
#pragma unroll
            for (int j = 0; j < 4; j++) {
                float4 t4 = ((float4*)rowp)[j];
                x[4*j+0] = t4.x; x[4*j+1] = t4.y; x[4*j+2] = t4.z; x[4*j+3] = t4.w;
            }
            float mt = x[0];
#pragma unroll
            for (int j = 1; j < 16; j++) mt = fmaxf(mt, x[j]);
            mt = fmaxf(mt, __shfl_xor_sync(0xffffffffu, mt, 1));
            mt = fmaxf(mt, __shfl_xor_sync(0xffffffffu, mt, 2));
            const float mprev = sm_m[r];
            const float mnew = fmaxf(mprev, mt);
            float sum = 0.f;
#pragma unroll
            for (int j = 0; j < 16; j++) { x[j] = fexp(x[j] - mnew); sum += x[j]; }
#pragma unroll
            for (int pjj = 0; pjj < 8; pjj++) {
                float e0 = x[2*pjj], e1 = x[2*pjj+1];
                uint32_t hp = pack_bf16(e0, e1);
                float f0 = __uint_as_float(hp << 16);
                float f1 = __uint_as_float(hp & 0xffff0000u);
                uint32_t lp = pack_bf16(e0 - f0, e1 - f1);
                *(uint32_t*)&Ph[r * PLD + qd * 16 + 2 * pjj] = hp;
                *(uint32_t*)&Pl[r * PLD + qd * 16 + 2 * pjj] = lp;
            }
            sum += __shfl_xor_sync(0xffffffffu, sum, 1);
            sum += __shfl_xor_sync(0xffffffffu, sum, 2);
            if (qd == 0) {
                const float sc = fexp(mprev - mnew);
                sm_scale[r] = sc;
                sm_l[r] = sm_l[r] * sc + sum;
                sm_m[r] = mnew;
            }
        }
        __syncthreads();

        // ---- rescale O accum, then O += P V (bf16 3x mma) ----
        {
            const float s0 = sm_scale[wm * 16 + g];
            const float s1 = sm_scale[wm * 16 + 8 + g];
#pragma unroll
            for (int nt = 0; nt < 4; nt++) {
                acc[nt][0] *= s0; acc[nt][1] *= s0;
                acc[nt][2] *= s1; acc[nt][3] *= s1;
            }
        }
#pragma unroll
        for (int ks = 0; ks < 4; ks++) {
            const int kk = ks * 16;
            const int m = wm * 16;
            uint32_t ah[4], al[4];
            ah[0] = *(const uint32_t*)&Ph[(m + g    ) * PLD + kk + 2 * tg    ];
            ah[1] = *(const uint32_t*)&Ph[(m + 8 + g) * PLD + kk + 2 * tg    ];
            ah[2] = *(const uint32_t*)&Ph[(m + g    ) * PLD + kk + 2 * tg + 8];
            ah[3] = *(const uint32_t*)&Ph[(m + 8 + g) * PLD + kk + 2 * tg + 8];
            al[0] = *(const uint32_t*)&Pl[(m + g    ) * PLD + kk + 2 * tg    ];
            al[1] = *(const uint32_t*)&Pl[(m + 8 + g) * PLD + kk + 2 * tg    ];
            al[2] = *(const uint32_t*)&Pl[(m + g    ) * PLD + kk + 2 * tg + 8];
            al[3] = *(const uint32_t*)&Pl[(m + 8 + g) * PLD + kk + 2 * tg + 8];
#pragma unroll
            for (int nt = 0; nt < 4; nt++) {
                const int n = wn * 32 + nt * 8 + g;
                uint32_t bh[2], bl[2];
                bh[0] = *(const uint32_t*)&Vh[n * PLD + kk + 2 * tg    ];
                bh[1] = *(const uint32_t*)&Vh[n * PLD + kk + 2 * tg + 8];
                bl[0] = *(const uint32_t*)&Vl[n * PLD + kk + 2 * tg    ];
                bl[1] = *(const uint32_t*)&Vl[n * PLD + kk + 2 * tg + 8];
                mma_bf16(acc[nt], ah, bh);
                mma_bf16(acc[nt], ah, bl);
                mma_bf16(acc[nt], al, bh);
            }
        }
        __syncthreads();
    }

    // ---- epilogue: normalize by l, write to g_o ----
    const float i0 = 1.0f / sm_l[wm * 16 + g];
    const float i1 = 1.0f / sm_l[wm * 16 + 8 + g];
    float* obase = g_o + (size_t)(b * Tt) * Dd + h * HDd;
    const int r = q0 + wm * 16 + g;
#pragma unroll
    for (int nt = 0; nt < 4; nt++) {
        const int c = wn * 32 + nt * 8 + tg * 2;
        float2 v0 = make_float2(acc[nt][0] * i0, acc[nt][1] * i0);
        float2 v1 = make_float2(acc[nt][2] * i1, acc[nt][3] * i1);
        *(float2*)&obase[(size_t)r * Dd + c]       = v0;
        *(float2*)&obase[(size_t)(r + 8) * Dd + c] = v1;
    }
}

// ---------------- KNN memory attention + gate -> exact bf16 ---------------------
__global__ __launch_bounds__(512) void memcomb_kernel(
    const float* __restrict__ mem_bank, const int* __restrict__ knn_idx,
    const float* __restrict__ gate_bias)
{
    const int t = blockIdx.x, b = blockIdx.y;
    const int h = threadIdx.x >> 5;
    const int lane = threadIdx.x & 31;
    const int row = b * Tt + t;
    const int d0 = h * HDd + lane;
    const int d1 = d0 + 32;

    const float* qrow = g_q + (size_t)row * Dd;
    const float qa = qrow[d0], qb = qrow[d1];

    int idx[3];
#pragma unroll
    for (int kk = 0; kk < 3; kk++) idx[kk] = knn_idx[row * Kknn + kk];

    float dots[3];
#pragma unroll
    for (int kk = 0; kk < 3; kk++) {
        const float* mk = mem_bank + ((size_t)(b * Mm + idx[kk]) * 2) * Dd;
        float p = qa * mk[d0] + qb * mk[d1];
#pragma unroll
        for (int o = 16; o; o >>= 1) p += __shfl_xor_sync(0xffffffffu, p, o);
        dots[kk] = p * SCALE_F;
    }
    float m = fmaxf(dots[0], fmaxf(dots[1], dots[2]));
    float w[3];
    w[0] = __expf(dots[0] - m);
    w[1] = __expf(dots[1] - m);
    w[2] = __expf(dots[2] - m);
    float inv = 1.0f / (w[0] + w[1] + w[2]);
    w[0] *= inv; w[1] *= inv; w[2] *= inv;

    float oa = 0.f, ob = 0.f;
#pragma unroll
    for (int kk = 0; kk < 3; kk++) {
        const float* mv = mem_bank + ((size_t)(b * Mm + idx[kk]) * 2 + 1) * Dd;
        oa = fmaf(w[kk], mv[d0], oa);
        ob = fmaf(w[kk], mv[d1], ob);
    }

    const float gbv = gate_bias[h];
    const float* orow = g_o + (size_t)row * Dd;
    float ca = oa * gbv + orow[d0] * (1.0f - gbv);
    float cb = ob * gbv + orow[d1] * (1.0f - gbv);
    g_obf[(size_t)row * Dd + d0] = __float2bfloat16(ca);
    g_obf[(size_t)row * Dd + d1] = __float2bfloat16(cb);
}

// -------------------------------- launch ----------------------------------------
extern "C" void kernel_launch(void* const* d_in, const int* in_sizes, int n_in,
                              void* d_out, int out_size)
{
    const float* x    = (const float*)d_in[0];
    const float* Wq   = (const float*)d_in[1];
    const float* bq   = (const float*)d_in[2];
    const float* Wk   = (const float*)d_in[3];
    const float* bk   = (const float*)d_in[4];
    const float* Wv   = (const float*)d_in[5];
    const float* bv   = (const float*)d_in[6];
    const float* Wo   = (const float*)d_in[7];
    const float* bo   = (const float*)d_in[8];
    const float* gate = (const float*)d_in[9];
    const float* mem  = (const float*)d_in[10];
    const int*   knn  = (const int*)d_in[11];
    float* out = (float*)d_out;

    float *q, *k, *v, *o;
    cudaGetSymbolAddress((void**)&q, g_q);
    cudaGetSymbolAddress((void**)&k, g_k);
    cudaGetSymbolAddress((void**)&v, g_v);
    cudaGetSymbolAddress((void**)&o, g_o);
    __nv_bfloat16 *obf, *xh, *xl, *wvh, *wvl, *woh, *wol;
    cudaGetSymbolAddress((void**)&obf, g_obf);
    cudaGetSymbolAddress((void**)&xh,  g_xh);
    cudaGetSymbolAddress((void**)&xl,  g_xl);
    cudaGetSymbolAddress((void**)&wvh, g_wvh);
    cudaGetSymbolAddress((void**)&wvl, g_wvl);
    cudaGetSymbolAddress((void**)&woh, g_woh);
    cudaGetSymbolAddress((void**)&wol, g_wol);
    float *xs, *wqs, *wks;
    cudaGetSymbolAddress((void**)&xs,  g_xs);
    cudaGetSymbolAddress((void**)&wqs, g_wqs);
    cudaGetSymbolAddress((void**)&wks, g_wks);

    // 0) pre-split planes: bf16 (V/out proj) and interleaved tf32 (Q/K proj)
    split_kernel<<<(Nn * Dd / 4 + 255) / 256, 256>>>(x, xh, xl, Nn * Dd / 4);
    split_kernel<<<(Dd * Dd / 4 + 255) / 256, 256>>>(Wv, wvh, wvl, Dd * Dd / 4);
    split_kernel<<<(Dd * Dd / 4 + 255) / 256, 256>>>(Wo, woh, wol, Dd * Dd / 4);
    split_tf32_kernel<<<(Nn * Dd / 4 + 255) / 256, 256>>>(x, xs, Nn * Dd / 4);
    split_tf32_kernel<<<(Dd * Dd / 4 + 255) / 256, 256>>>(Wq, wqs, Dd * Dd / 4);
    split_tf32_kernel<<<(Dd * Dd / 4 + 255) / 256, 256>>>(Wk, wks, Dd * Dd / 4);

    // 1) Q, K projections (3xTF32, pre-split planes)
    {
        dim3 grid(Dd / 128, Nn / 128, 2);
        gemm_tf32ps_kernel<<<grid, 256>>>(xs, wqs, bq, q, wks, bk, k);
    }
    // 1b) V projection (bf16 3x)
    {
        dim3 grid(Dd / 128, Nn / 128, 1);
        gemm_bf16_kernel<1><<<grid, 256>>>(xh, xl, wvh, wvl, bv, v);
    }
    // 2) normalize q, k rows
    {
        dim3 grid(Nn, 2);
        normalize_kernel<<<grid, 256>>>();
    }
    // 3) causal flash attention
    {
        const int smem_bytes = 4 * 64 * ALD * (int)sizeof(float)
                             + 4 * 64 * PLD * (int)sizeof(uint16_t);
        cudaFuncSetAttribute(attn_kernel,
                             cudaFuncAttributeMaxDynamicSharedMemorySize, smem_bytes);
        dim3 grid(Tt / 64, Hh, Bb);
        attn_kernel<<<grid, 256, smem_bytes>>>();
    }
    // 4) KNN memory attention + gate -> exact bf16 combined
    {
        dim3 grid(Tt, Bb);
        memcomb_kernel<<<grid, 512>>>(mem, knn, gate);
    }
    // 5) output projection (bf16 2x: A exact in bf16) -> d_out
    {
        dim3 grid(Dd / 128, Nn / 128, 1);
        gemm_bf16_kernel<0><<<grid, 256>>>(obf, nullptr, woh, wol, bo, out);
    }
}